// round 3
// baseline (speedup 1.0000x reference)
#include <cuda_runtime.h>
#include <math.h>

#define BATCH 8
#define HEADS 8
#define SEQ   1024
#define DIM   512
#define DH    64
#define INNER 512
#define BH    (BATCH*HEADS)   // 64
#define WGRID 32

// ---------------- scratch (no allocations allowed) ----------------
__device__ float g_xn[(size_t)BATCH*SEQ*DIM];      // 16 MB
__device__ float g_q [(size_t)BH*SEQ*DH];          // 16 MB
__device__ float g_kt[(size_t)BH*DH*SEQ];          // 16 MB (K pre-transposed)
__device__ float g_v [(size_t)BH*SEQ*DH];          // 16 MB
__device__ float g_s [(size_t)BH*SEQ*SEQ];         // 256 MB (scores -> weights)
__device__ float g_o [(size_t)BATCH*SEQ*INNER];    // 16 MB

// ---------------- LayerNorm ----------------
__global__ void ln_kernel(const float* __restrict__ x,
                          const float* __restrict__ gam,
                          const float* __restrict__ bet) {
    int row = blockIdx.x;                     // 0..8191
    const float* xr = x + (size_t)row * DIM;
    float* outp = g_xn + (size_t)row * DIM;
    int t = threadIdx.x;                      // 128 threads
    float v[4];
    float s = 0.f, ss = 0.f;
#pragma unroll
    for (int i = 0; i < 4; i++) {
        v[i] = xr[t + i*128];
        s  += v[i];
        ss += v[i]*v[i];
    }
#pragma unroll
    for (int o = 16; o; o >>= 1) {
        s  += __shfl_xor_sync(0xffffffffu, s, o);
        ss += __shfl_xor_sync(0xffffffffu, ss, o);
    }
    __shared__ float sb[2][4];
    int warp = t >> 5, lane = t & 31;
    if (lane == 0) { sb[0][warp] = s; sb[1][warp] = ss; }
    __syncthreads();
    s  = sb[0][0]+sb[0][1]+sb[0][2]+sb[0][3];
    ss = sb[1][0]+sb[1][1]+sb[1][2]+sb[1][3];
    float mean = s * (1.0f/DIM);
    float var  = ss * (1.0f/DIM) - mean*mean;
    float inv  = rsqrtf(var + 1e-5f);
#pragma unroll
    for (int i = 0; i < 4; i++) {
        int c = t + i*128;
        outp[c] = (v[i]-mean)*inv*gam[c] + bet[c];
    }
}

// ---------------- generic tiled GEMM core (exact-tile dims only) ----------------
template<int BM,int BN,int BK,int TM,int TN>
__device__ __forceinline__ void gemm_block(const float* __restrict__ A,
                                           const float* __restrict__ B,
                                           int K, int lda, int ldb,
                                           float acc[TM][TN]) {
    __shared__ float As[BK][BM];
    __shared__ float Bs[BK][BN];
    const int tid  = threadIdx.x;            // 256 threads
    const int tx   = tid % (BN/TN);
    const int ty   = tid / (BN/TN);
    const int row0 = blockIdx.y * BM;
    const int col0 = blockIdx.x * BN;
#pragma unroll
    for (int i = 0; i < TM; i++)
#pragma unroll
        for (int j = 0; j < TN; j++) acc[i][j] = 0.f;

    for (int k0 = 0; k0 < K; k0 += BK) {
#pragma unroll
        for (int idx = tid; idx < BM*BK; idx += 256) {
            int r = idx / BK, c = idx % BK;
            As[c][r] = A[(size_t)(row0+r)*lda + (k0+c)];
        }
#pragma unroll
        for (int idx = tid; idx < BK*BN; idx += 256) {
            int r = idx / BN, c = idx % BN;
            Bs[r][c] = B[(size_t)(k0+r)*ldb + (col0+c)];
        }
        __syncthreads();
#pragma unroll
        for (int kk = 0; kk < BK; kk++) {
            float ra[TM], rb[TN];
#pragma unroll
            for (int i = 0; i < TM; i++) ra[i] = As[kk][ty*TM+i];
#pragma unroll
            for (int j = 0; j < TN; j++) rb[j] = Bs[kk][tx*TN+j];
#pragma unroll
            for (int i = 0; i < TM; i++)
#pragma unroll
                for (int j = 0; j < TN; j++)
                    acc[i][j] += ra[i]*rb[j];
        }
        __syncthreads();
    }
}

// ---------------- QKV projection + scatter epilogue ----------------
__global__ __launch_bounds__(256) void qkv_gemm(const float* __restrict__ w,
                                                const float* __restrict__ bias) {
    float acc[8][8];
    gemm_block<128,128,8,8,8>(g_xn, w, DIM, DIM, 3*INNER, acc);
    int tx = threadIdx.x % 16, ty = threadIdx.x / 16;
    int row0 = blockIdx.y*128 + ty*8;
    int col0 = blockIdx.x*128 + tx*8;
#pragma unroll
    for (int i = 0; i < 8; i++) {
        int r  = row0 + i;
        int bb = r >> 10, nn = r & 1023;
#pragma unroll
        for (int j = 0; j < 8; j++) {
            int c = col0 + j;
            float val = acc[i][j] + bias[c];
            int sec = c >> 9, rem = c & 511;
            int h = rem >> 6, d = rem & 63;
            int bh = bb*HEADS + h;
            if (sec == 0)
                g_q[((size_t)bh*SEQ + nn)*DH + d] = val;
            else if (sec == 1)
                g_kt[((size_t)bh*DH + d)*SEQ + nn] = val;   // transposed
            else
                g_v[((size_t)bh*SEQ + nn)*DH + d] = val;
        }
    }
}

// ---------------- scores: S = Q @ K^T * scale (per b,h) ----------------
__global__ __launch_bounds__(256) void scores_gemm() {
    int z = blockIdx.z;
    float acc[8][8];
    gemm_block<128,128,8,8,8>(g_q + (size_t)z*SEQ*DH,
                              g_kt + (size_t)z*DH*SEQ,
                              DH, DH, SEQ, acc);
    int tx = threadIdx.x % 16, ty = threadIdx.x / 16;
    int row0 = blockIdx.y*128 + ty*8;
    int col0 = blockIdx.x*128 + tx*8;
    float* S = g_s + (size_t)z*SEQ*SEQ;
#pragma unroll
    for (int i = 0; i < 8; i++)
#pragma unroll
        for (int j = 0; j < 8; j++)
            S[(size_t)(row0+i)*SEQ + (col0+j)] = acc[i][j] * 0.125f;
}

// ---------------- combined 4-region softmax weights (in-place on S) ----------------
__global__ __launch_bounds__(256) void weights_kernel() {
    int q = blockIdx.x;       // 0..1023
    int z = blockIdx.y;       // 0..63
    float* srow = g_s + ((size_t)z*SEQ + q)*SEQ;
    int t = threadIdx.x;      // 256 threads, 4 keys each
    int r = q >> 5, c = q & 31;

    float sv[4];
    bool  m[4][4];
    float mx[4] = {-1e30f,-1e30f,-1e30f,-1e30f};
#pragma unroll
    for (int i = 0; i < 4; i++) {
        int k = t + i*256;
        sv[i] = srow[k];
        int ki = k >> 5, kj = k & 31;
        bool ler = (ki <= r), ger = (ki >= r);
        bool lec = (kj <= c), gec = (kj >= c);
        m[i][0] = ler && lec;
        m[i][1] = ler && gec;
        m[i][2] = ger && lec;
        m[i][3] = ger && gec;
#pragma unroll
        for (int rg = 0; rg < 4; rg++)
            if (m[i][rg]) mx[rg] = fmaxf(mx[rg], sv[i]);
    }

    __shared__ float red[8];
    int warp = t >> 5, lane = t & 31;
    // block-reduce 4 maxes
#pragma unroll
    for (int rg = 0; rg < 4; rg++) {
        float v = mx[rg];
#pragma unroll
        for (int o = 16; o; o >>= 1) v = fmaxf(v, __shfl_xor_sync(0xffffffffu, v, o));
        if (lane == 0) red[warp] = v;
        __syncthreads();
        float mm = red[0];
#pragma unroll
        for (int w = 1; w < 8; w++) mm = fmaxf(mm, red[w]);
        mx[rg] = mm;
        __syncthreads();
    }
    // masked exp sums
    float zs[4] = {0.f,0.f,0.f,0.f};
#pragma unroll
    for (int i = 0; i < 4; i++)
#pragma unroll
        for (int rg = 0; rg < 4; rg++)
            if (m[i][rg]) zs[rg] += __expf(sv[i]-mx[rg]);
#pragma unroll
    for (int rg = 0; rg < 4; rg++) {
        float v = zs[rg];
#pragma unroll
        for (int o = 16; o; o >>= 1) v += __shfl_xor_sync(0xffffffffu, v, o);
        if (lane == 0) red[warp] = v;
        __syncthreads();
        float ssum = 0.f;
#pragma unroll
        for (int w = 0; w < 8; w++) ssum += red[w];
        zs[rg] = 0.25f / ssum;     // fold the final /4
        __syncthreads();
    }
    // combined weights
#pragma unroll
    for (int i = 0; i < 4; i++) {
        int k = t + i*256;
        float wv = 0.f;
#pragma unroll
        for (int rg = 0; rg < 4; rg++)
            if (m[i][rg]) wv += __expf(sv[i]-mx[rg]) * zs[rg];
        srow[k] = wv;
    }
}

// ---------------- AV: O = W @ V (per b,h) ----------------
__global__ __launch_bounds__(256) void av_gemm() {
    int z = blockIdx.z;
    float acc[8][4];
    gemm_block<128,64,8,8,4>(g_s + (size_t)z*SEQ*SEQ,
                             g_v + (size_t)z*SEQ*DH,
                             SEQ, SEQ, DH, acc);
    int tx = threadIdx.x % 16, ty = threadIdx.x / 16;
    int row0 = blockIdx.y*128 + ty*8;
    int col0 = blockIdx.x*64  + tx*4;
    int bb = z / HEADS, h = z % HEADS;
#pragma unroll
    for (int i = 0; i < 8; i++) {
        int n = row0 + i;
        float* op = g_o + ((size_t)bb*SEQ + n)*INNER + h*DH;
#pragma unroll
        for (int j = 0; j < 4; j++)
            op[col0+j] = acc[i][j];
    }
}

// ---------------- output projection ----------------
__global__ __launch_bounds__(256) void out_gemm(const float* __restrict__ w,
                                                const float* __restrict__ bias,
                                                float* __restrict__ outp) {
    float acc[8][8];
    gemm_block<128,128,8,8,8>(g_o, w, INNER, INNER, DIM, acc);
    int tx = threadIdx.x % 16, ty = threadIdx.x / 16;
    int row0 = blockIdx.y*128 + ty*8;
    int col0 = blockIdx.x*128 + tx*8;
#pragma unroll
    for (int i = 0; i < 8; i++)
#pragma unroll
        for (int j = 0; j < 8; j++)
            outp[(size_t)(row0+i)*DIM + (col0+j)] = acc[i][j] + bias[col0+j];
}

// ---------------- launch ----------------
extern "C" void kernel_launch(void* const* d_in, const int* in_sizes, int n_in,
                              void* d_out, int out_size) {
    const float* x     = (const float*)d_in[0];
    const float* ln_g  = (const float*)d_in[1];
    const float* ln_b  = (const float*)d_in[2];
    const float* w_qkv = (const float*)d_in[3];
    const float* b_qkv = (const float*)d_in[4];
    const float* w_out = (const float*)d_in[5];
    const float* b_out = (const float*)d_in[6];
    float* outp = (float*)d_out;

    ln_kernel<<<BATCH*SEQ, 128>>>(x, ln_g, ln_b);
    qkv_gemm<<<dim3((3*INNER)/128, (BATCH*SEQ)/128), 256>>>(w_qkv, b_qkv);
    scores_gemm<<<dim3(SEQ/128, SEQ/128, BH), 256>>>();
    weights_kernel<<<dim3(SEQ, BH), 256>>>();
    av_gemm<<<dim3(1, SEQ/128, BH), 256>>>();
    out_gemm<<<dim3(DIM/128, (BATCH*SEQ)/128), 256>>>(w_out, b_out, outp);
}

// round 5
// speedup vs baseline: 3.6671x; 3.6671x over previous
#include <cuda_runtime.h>
#include <math.h>
#include <stdint.h>

#define BATCH 8
#define HEADS 8
#define SEQ   1024
#define DIM   512
#define DH    64
#define INNER 512
#define BH    (BATCH*HEADS)   // 64

// ---------------- scratch (no allocations allowed) ----------------
__device__ float g_xn[(size_t)BATCH*SEQ*DIM];      // 16 MB
__device__ float g_q [(size_t)BH*SEQ*DH];          // 16 MB
__device__ float g_kt[(size_t)BH*DH*SEQ];          // 16 MB (K pre-transposed)
__device__ float g_v [(size_t)BH*SEQ*DH];          // 16 MB
__device__ float g_s [(size_t)BH*SEQ*SEQ];         // 256 MB (scores -> weights)
__device__ float g_o [(size_t)BATCH*SEQ*INNER];    // 16 MB

// ---------------- helpers ----------------
__device__ __forceinline__ uint32_t f2tf32(float f) {
    uint32_t u;
    asm("cvt.rna.tf32.f32 %0, %1;" : "=r"(u) : "f"(f));
    return u;
}

__device__ __forceinline__ void mma_tf32(float c[4],
                                         const uint32_t a[4],
                                         const uint32_t b[2]) {
    asm volatile(
        "mma.sync.aligned.m16n8k8.row.col.f32.tf32.tf32.f32 "
        "{%0,%1,%2,%3}, {%4,%5,%6,%7}, {%8,%9}, {%0,%1,%2,%3};"
        : "+f"(c[0]), "+f"(c[1]), "+f"(c[2]), "+f"(c[3])
        : "r"(a[0]), "r"(a[1]), "r"(a[2]), "r"(a[3]),
          "r"(b[0]), "r"(b[1]));
}

// ---------------- LayerNorm ----------------
__global__ void ln_kernel(const float* __restrict__ x,
                          const float* __restrict__ gam,
                          const float* __restrict__ bet) {
    int row = blockIdx.x;
    const float* xr = x + (size_t)row * DIM;
    float* outp = g_xn + (size_t)row * DIM;
    int t = threadIdx.x;                      // 128 threads
    float v[4];
    float s = 0.f, ss = 0.f;
#pragma unroll
    for (int i = 0; i < 4; i++) {
        v[i] = xr[t + i*128];
        s  += v[i];
        ss += v[i]*v[i];
    }
#pragma unroll
    for (int o = 16; o; o >>= 1) {
        s  += __shfl_xor_sync(0xffffffffu, s, o);
        ss += __shfl_xor_sync(0xffffffffu, ss, o);
    }
    __shared__ float sb[2][4];
    int warp = t >> 5, lane = t & 31;
    if (lane == 0) { sb[0][warp] = s; sb[1][warp] = ss; }
    __syncthreads();
    s  = sb[0][0]+sb[0][1]+sb[0][2]+sb[0][3];
    ss = sb[1][0]+sb[1][1]+sb[1][2]+sb[1][3];
    float mean = s * (1.0f/DIM);
    float var  = ss * (1.0f/DIM) - mean*mean;
    float inv  = rsqrtf(var + 1e-5f);
#pragma unroll
    for (int i = 0; i < 4; i++) {
        int c = t + i*128;
        outp[c] = (v[i]-mean)*inv*gam[c] + bet[c];
    }
}

// ---------------- TF32 tensor-core GEMM core ----------------
// 256 threads, 8 warps arranged (BM/WM) x (BN/WN). Each warp: WM x WN.
// Fragment layouts per PTX mma.m16n8k8:
//   A row-major: a0=[g][tg] a1=[g+8][tg] a2=[g][tg+4] a3=[g+8][tg+4]
//   B col-major: b0=[k=tg][n=g] b1=[k=tg+4][n=g]
//   C: c0=[g][2tg] c1=[g][2tg+1] c2=[g+8][2tg] c3=[g+8][2tg+1]
template<int BM,int BN,int BK,int WM,int WN>
__device__ __forceinline__ void mma_gemm_core(
    const float* __restrict__ A, const float* __restrict__ B,
    int K, int lda, int ldb, int row0, int col0,
    float acc[WM/16][WN/8][4])
{
    constexpr int MI = WM/16, NI = WN/8;
    constexpr int WCOLS = BN/WN;
    __shared__ uint32_t As[BM][BK+4];   // conflict-free for frag loads
    __shared__ uint32_t Bs[BK][BN+8];
    const int tid  = threadIdx.x;
    const int lane = tid & 31, wid = tid >> 5;
    const int g = lane >> 2, tg = lane & 3;
    const int wr = wid / WCOLS, wc = wid % WCOLS;

#pragma unroll
    for (int mi = 0; mi < MI; mi++)
#pragma unroll
        for (int ni = 0; ni < NI; ni++)
#pragma unroll
            for (int rr = 0; rr < 4; rr++) acc[mi][ni][rr] = 0.f;

    for (int k0 = 0; k0 < K; k0 += BK) {
        // load A tile (BM x BK), transpose-free layout [m][k], tf32-convert once
#pragma unroll
        for (int s = 0; s < BM*BK/4; s += 256) {
            int slot = s + tid;
            int r  = slot / (BK/4);
            int kq = slot % (BK/4);
            float4 v = *(const float4*)(A + (size_t)(row0+r)*lda + k0 + kq*4);
            As[r][kq*4+0] = f2tf32(v.x);
            As[r][kq*4+1] = f2tf32(v.y);
            As[r][kq*4+2] = f2tf32(v.z);
            As[r][kq*4+3] = f2tf32(v.w);
        }
        // load B tile (BK x BN), layout [k][n]
#pragma unroll
        for (int s = 0; s < BK*BN/4; s += 256) {
            int slot = s + tid;
            int kr = slot / (BN/4);
            int nc = slot % (BN/4);
            float4 v = *(const float4*)(B + (size_t)(k0+kr)*ldb + col0 + nc*4);
            uint4 u;
            u.x = f2tf32(v.x); u.y = f2tf32(v.y);
            u.z = f2tf32(v.z); u.w = f2tf32(v.w);
            *(uint4*)&Bs[kr][nc*4] = u;
        }
        __syncthreads();
#pragma unroll
        for (int ks = 0; ks < BK/8; ks++) {
            uint32_t af[MI][4], bf[NI][2];
#pragma unroll
            for (int mi = 0; mi < MI; mi++) {
                int m0 = wr*WM + mi*16;
                af[mi][0] = As[m0+g  ][ks*8+tg  ];
                af[mi][1] = As[m0+g+8][ks*8+tg  ];
                af[mi][2] = As[m0+g  ][ks*8+tg+4];
                af[mi][3] = As[m0+g+8][ks*8+tg+4];
            }
#pragma unroll
            for (int ni = 0; ni < NI; ni++) {
                int n0 = wc*WN + ni*8;
                bf[ni][0] = Bs[ks*8+tg  ][n0+g];
                bf[ni][1] = Bs[ks*8+tg+4][n0+g];
            }
#pragma unroll
            for (int mi = 0; mi < MI; mi++)
#pragma unroll
                for (int ni = 0; ni < NI; ni++)
                    mma_tf32(acc[mi][ni], af[mi], bf[ni]);
        }
        __syncthreads();
    }
}

// ---------------- QKV projection + scatter epilogue ----------------
__global__ __launch_bounds__(256) void qkv_gemm(const float* __restrict__ w,
                                                const float* __restrict__ bias) {
    constexpr int WM = 64, WN = 32, MI = WM/16, NI = WN/8;
    float acc[MI][NI][4];
    int row0 = blockIdx.y*128, col0 = blockIdx.x*128;
    mma_gemm_core<128,128,16,WM,WN>(g_xn, w, DIM, DIM, 3*INNER, row0, col0, acc);

    const int lane = threadIdx.x & 31, wid = threadIdx.x >> 5;
    const int g = lane >> 2, tg = lane & 3;
    const int wr = wid / 4, wc = wid % 4;
#pragma unroll
    for (int mi = 0; mi < MI; mi++)
#pragma unroll
        for (int ni = 0; ni < NI; ni++)
#pragma unroll
            for (int rr = 0; rr < 4; rr++) {
                int r = row0 + wr*WM + mi*16 + g + (rr>>1)*8;
                int c = col0 + wc*WN + ni*8 + tg*2 + (rr&1);
                float val = acc[mi][ni][rr] + bias[c];
                int bb = r >> 10, nn = r & 1023;
                int sec = c >> 9, rem = c & 511;
                int h = rem >> 6, d = rem & 63;
                int bh = bb*HEADS + h;
                if (sec == 0)
                    g_q[((size_t)bh*SEQ + nn)*DH + d] = val;
                else if (sec == 1)
                    g_kt[((size_t)bh*DH + d)*SEQ + nn] = val;   // transposed
                else
                    g_v[((size_t)bh*SEQ + nn)*DH + d] = val;
            }
}

// ---------------- scores: S = Q @ K^T * scale (per b,h) ----------------
__global__ __launch_bounds__(256) void scores_gemm() {
    constexpr int WM = 64, WN = 32, MI = WM/16, NI = WN/8;
    int z = blockIdx.z;
    float acc[MI][NI][4];
    int row0 = blockIdx.y*128, col0 = blockIdx.x*128;
    mma_gemm_core<128,128,16,WM,WN>(g_q + (size_t)z*SEQ*DH,
                                    g_kt + (size_t)z*DH*SEQ,
                                    DH, DH, SEQ, row0, col0, acc);
    const int lane = threadIdx.x & 31, wid = threadIdx.x >> 5;
    const int g = lane >> 2, tg = lane & 3;
    const int wr = wid / 4, wc = wid % 4;
    float* S = g_s + (size_t)z*SEQ*SEQ;
#pragma unroll
    for (int mi = 0; mi < MI; mi++)
#pragma unroll
        for (int ni = 0; ni < NI; ni++)
#pragma unroll
            for (int rr = 0; rr < 4; rr++) {
                int r = row0 + wr*WM + mi*16 + g + (rr>>1)*8;
                int c = col0 + wc*WN + ni*8 + tg*2 + (rr&1);
                S[(size_t)r*SEQ + c] = acc[mi][ni][rr] * 0.125f;
            }
}

// ---------------- combined 4-region softmax weights (warp per query row) ----
// With one global row max M:  w_k = exp(s_k - M) * sum_{regions containing k} (1/4)/Z_rg
// Region sums are separable: per-lane (fixed kj) column sums over ki<=r / ki>=r,
// then 4 predicated warp reductions over kj<=c / kj>=c.
__global__ __launch_bounds__(256) void weights_kernel() {
    int wid = threadIdx.x >> 5, lane = threadIdx.x & 31;
    int q = blockIdx.x * 8 + wid;
    int z = blockIdx.y;
    float* srow = g_s + ((size_t)z*SEQ + q)*SEQ;
    int r = q >> 5, c = q & 31;
    int kj = lane;

    float e[32];
    float M = -1e30f;
#pragma unroll
    for (int ki = 0; ki < 32; ki++) {
        e[ki] = srow[ki*32 + kj];              // coalesced 128B per row
        M = fmaxf(M, e[ki]);
    }
#pragma unroll
    for (int o = 16; o; o >>= 1)
        M = fmaxf(M, __shfl_xor_sync(0xffffffffu, M, o));

    float cle = 0.f, cge = 0.f;                // column sums split at r
#pragma unroll
    for (int ki = 0; ki < 32; ki++) {
        e[ki] = __expf(e[ki] - M);
        if (ki <= r) cle += e[ki];
        if (ki >= r) cge += e[ki];
    }
    bool jle = (kj <= c), jge = (kj >= c);
    float z00 = jle ? cle : 0.f;               // region (ki<=r, kj<=c)
    float z01 = jge ? cle : 0.f;               // (ki<=r, kj>=c)
    float z10 = jle ? cge : 0.f;               // (ki>=r, kj<=c)
    float z11 = jge ? cge : 0.f;               // (ki>=r, kj>=c)
#pragma unroll
    for (int o = 16; o; o >>= 1) {
        z00 += __shfl_xor_sync(0xffffffffu, z00, o);
        z01 += __shfl_xor_sync(0xffffffffu, z01, o);
        z10 += __shfl_xor_sync(0xffffffffu, z10, o);
        z11 += __shfl_xor_sync(0xffffffffu, z11, o);
    }
    float ct = (jle ? 0.25f/z00 : 0.f) + (jge ? 0.25f/z01 : 0.f);
    float cb = (jle ? 0.25f/z10 : 0.f) + (jge ? 0.25f/z11 : 0.f);
#pragma unroll
    for (int ki = 0; ki < 32; ki++) {
        float wv = e[ki] * ((ki <= r ? ct : 0.f) + (ki >= r ? cb : 0.f));
        srow[ki*32 + kj] = wv;
    }
}

// ---------------- AV: O = W @ V (per b,h) ----------------
__global__ __launch_bounds__(256) void av_gemm() {
    constexpr int WM = 32, WN = 32, MI = WM/16, NI = WN/8;
    int z = blockIdx.z;
    float acc[MI][NI][4];
    int row0 = blockIdx.y*128, col0 = 0;
    mma_gemm_core<128,64,16,WM,WN>(g_s + (size_t)z*SEQ*SEQ,
                                   g_v + (size_t)z*SEQ*DH,
                                   SEQ, SEQ, DH, row0, col0, acc);
    const int lane = threadIdx.x & 31, wid = threadIdx.x >> 5;
    const int g = lane >> 2, tg = lane & 3;
    const int wr = wid / 2, wc = wid % 2;
    int bb = z / HEADS, h = z % HEADS;
#pragma unroll
    for (int mi = 0; mi < MI; mi++)
#pragma unroll
        for (int ni = 0; ni < NI; ni++)
#pragma unroll
            for (int rr = 0; rr < 4; rr++) {
                int n = row0 + wr*WM + mi*16 + g + (rr>>1)*8;
                int d = wc*WN + ni*8 + tg*2 + (rr&1);
                g_o[((size_t)bb*SEQ + n)*INNER + h*DH + d] = acc[mi][ni][rr];
            }
}

// ---------------- output projection ----------------
__global__ __launch_bounds__(256) void out_gemm(const float* __restrict__ w,
                                                const float* __restrict__ bias,
                                                float* __restrict__ outp) {
    constexpr int WM = 64, WN = 32, MI = WM/16, NI = WN/8;
    float acc[MI][NI][4];
    int row0 = blockIdx.y*128, col0 = blockIdx.x*128;
    mma_gemm_core<128,128,16,WM,WN>(g_o, w, INNER, INNER, DIM, row0, col0, acc);
    const int lane = threadIdx.x & 31, wid = threadIdx.x >> 5;
    const int g = lane >> 2, tg = lane & 3;
    const int wr = wid / 4, wc = wid % 4;
#pragma unroll
    for (int mi = 0; mi < MI; mi++)
#pragma unroll
        for (int ni = 0; ni < NI; ni++)
#pragma unroll
            for (int rr = 0; rr < 4; rr++) {
                int r = row0 + wr*WM + mi*16 + g + (rr>>1)*8;
                int c = col0 + wc*WN + ni*8 + tg*2 + (rr&1);
                outp[(size_t)r*DIM + c] = acc[mi][ni][rr] + bias[c];
            }
}

// ---------------- launch ----------------
extern "C" void kernel_launch(void* const* d_in, const int* in_sizes, int n_in,
                              void* d_out, int out_size) {
    const float* x     = (const float*)d_in[0];
    const float* ln_g  = (const float*)d_in[1];
    const float* ln_b  = (const float*)d_in[2];
    const float* w_qkv = (const float*)d_in[3];
    const float* b_qkv = (const float*)d_in[4];
    const float* w_out = (const float*)d_in[5];
    const float* b_out = (const float*)d_in[6];
    float* outp = (float*)d_out;

    ln_kernel<<<BATCH*SEQ, 128>>>(x, ln_g, ln_b);
    qkv_gemm<<<dim3((3*INNER)/128, (BATCH*SEQ)/128), 256>>>(w_qkv, b_qkv);
    scores_gemm<<<dim3(SEQ/128, SEQ/128, BH), 256>>>();
    weights_kernel<<<dim3(SEQ/8, BH), 256>>>();
    av_gemm<<<dim3(1, SEQ/128, BH), 256>>>();
    out_gemm<<<dim3(DIM/128, (BATCH*SEQ)/128), 256>>>(w_out, b_out, outp);
}